// round 2
// baseline (speedup 1.0000x reference)
#include <cuda_runtime.h>
#include <cuda_bf16.h>
#include <math.h>

// Problem constants
#define BATCH   4
#define CH      64
#define IMG_W   256
#define IMG_H   256
#define HW      (IMG_W * IMG_H)        // 65536
#define WP      128
#define HWP     (WP * WP)              // 16384

// ---------------------------------------------------------------------------
// Static device scratch (no runtime allocation allowed)
// ---------------------------------------------------------------------------
__device__ float g_xh[BATCH * CH * HW];    // DW1(x)
__device__ float g_yh[BATCH * CH * HW];    // DW2(y)
__device__ float g_xp[BATCH * CH * HWP];   // avgpool2(x)
__device__ float g_yp[BATCH * CH * HWP];   // avgpool2(y)
__device__ float g_Gh [BATCH * 4096];      // xh · yh^T
__device__ float g_Gxy[BATCH * 4096];      // xp · yp^T
__device__ float g_Gxx[BATCH * 4096];      // xp · xp^T
__device__ float g_Gyy[BATCH * 4096];      // yp · yp^T
__device__ float g_M  [BATCH * 2 * 4096];  // per batch: M1 (4096), M2 (4096)

// ---------------------------------------------------------------------------
// zero the gram accumulators
// ---------------------------------------------------------------------------
__global__ void zero_kernel() {
    int i = blockIdx.x * blockDim.x + threadIdx.x;
    if (i < BATCH * 4096) {
        g_Gh[i] = 0.f; g_Gxy[i] = 0.f; g_Gxx[i] = 0.f; g_Gyy[i] = 0.f;
    }
}

// ---------------------------------------------------------------------------
// Depthwise conv (k=3/5/7 per channel group) + 2x2 avg pool of the raw input.
// grid: (16 tiles, 64 channels, 4 batches); block: 256
// sel = 0 -> write g_xh/g_xp, sel = 1 -> write g_yh/g_yp
// ---------------------------------------------------------------------------
template<int K>
__device__ __forceinline__ void dw_compute(const float* __restrict__ s,
                                           const float* __restrict__ wp,
                                           float* __restrict__ outh,
                                           int ty0, int tx0, int tid)
{
    float wr[K * K];
#pragma unroll
    for (int t = 0; t < K * K; t++) wr[t] = __ldg(&wp[t]);

    int col = tid & 63;
    int rb  = tid >> 6;
#pragma unroll 4
    for (int i = 0; i < 16; i++) {
        int row = rb + 4 * i;
        float acc = 0.f;
#pragma unroll
        for (int dy = 0; dy < K; dy++) {
#pragma unroll
            for (int dx = 0; dx < K; dx++) {
                acc += wr[dy * K + dx] *
                       s[(row + 3 - K / 2 + dy) * 70 + (col + 3 - K / 2 + dx)];
            }
        }
        outh[(ty0 + row) * IMG_W + tx0 + col] = acc;
    }
}

__global__ __launch_bounds__(256)
void dwpool_kernel(const float* __restrict__ img,
                   const float* __restrict__ w3,
                   const float* __restrict__ w5,
                   const float* __restrict__ w7,
                   int sel)
{
    __shared__ float s[70 * 70];
    int tile = blockIdx.x;          // 0..15 (4x4 tiles of 64x64)
    int c    = blockIdx.y;
    int b    = blockIdx.z;
    int tid  = threadIdx.x;

    int ty0 = (tile >> 2) * 64;
    int tx0 = (tile & 3) * 64;

    const float* base = img + ((size_t)(b * CH + c)) * HW;

    for (int idx = tid; idx < 70 * 70; idx += 256) {
        int r  = idx / 70, q = idx % 70;
        int gy = ty0 + r - 3, gx = tx0 + q - 3;
        float v = 0.f;
        if (gy >= 0 && gy < IMG_H && gx >= 0 && gx < IMG_W)
            v = __ldg(&base[gy * IMG_W + gx]);
        s[idx] = v;
    }
    __syncthreads();

    float* outh = (sel == 0 ? g_xh : g_yh) + ((size_t)(b * CH + c)) * HW;
    float* outp = (sel == 0 ? g_xp : g_yp) + ((size_t)(b * CH + c)) * HWP;

    if (c < 32) {
        dw_compute<3>(s, w3 + c * 9, outh, ty0, tx0, tid);
    } else if (c < 48) {
        dw_compute<5>(s, w5 + (c - 32) * 25, outh, ty0, tx0, tid);
    } else {
        dw_compute<7>(s, w7 + (c - 48) * 49, outh, ty0, tx0, tid);
    }

    // 2x2 average pooling of raw input from smem (32x32 pooled values per tile)
    int pty0 = ty0 >> 1, ptx0 = tx0 >> 1;
#pragma unroll
    for (int i = 0; i < 4; i++) {
        int p  = tid + 256 * i;          // 0..1023
        int pr = p >> 5, pc = p & 31;
        float v = 0.25f * (s[(2 * pr + 3) * 70 + (2 * pc + 3)] +
                           s[(2 * pr + 3) * 70 + (2 * pc + 4)] +
                           s[(2 * pr + 4) * 70 + (2 * pc + 3)] +
                           s[(2 * pr + 4) * 70 + (2 * pc + 4)]);
        outp[(pty0 + pr) * WP + ptx0 + pc] = v;
    }
}

// ---------------------------------------------------------------------------
// Gram: G[b][c1][c2] = sum_n A[b][c1][n] * B[b][c2][n]
// which: 0 -> (xh,yh)->Gh   1 -> (xp,yp)->Gxy   2 -> (xp,xp)->Gxx   3 -> (yp,yp)->Gyy
// grid: (chunks, BATCH); block 256. Each thread owns an 8x8 subtile.
// ---------------------------------------------------------------------------
__global__ __launch_bounds__(256)
void gram64_kernel(int which, int npix, int chunks)
{
    __shared__ float As[64][65];
    __shared__ float Bs[64][65];

    const float* A; const float* Bm; float* G;
    if (which == 0)      { A = g_xh; Bm = g_yh; G = g_Gh;  }
    else if (which == 1) { A = g_xp; Bm = g_yp; G = g_Gxy; }
    else if (which == 2) { A = g_xp; Bm = g_xp; G = g_Gxx; }
    else                 { A = g_yp; Bm = g_yp; G = g_Gyy; }

    int b   = blockIdx.y;
    int tid = threadIdx.x;
    int per = npix / chunks;
    int n_start = blockIdx.x * per;
    int n_end   = n_start + per;

    const float* Ab = A  + (size_t)b * CH * npix;
    const float* Bb = Bm + (size_t)b * CH * npix;

    int i8 = (tid >> 3) & 7;   // c1 group
    int j8 = tid & 7;          // c2 group
    int ps = tid >> 6;         // pixel slice 0..3

    float acc[8][8];
#pragma unroll
    for (int u = 0; u < 8; u++)
#pragma unroll
        for (int v = 0; v < 8; v++) acc[u][v] = 0.f;

    for (int n0 = n_start; n0 < n_end; n0 += 64) {
        __syncthreads();
        for (int idx = tid; idx < 4096; idx += 256) {
            int cc = idx >> 6, p = idx & 63;
            As[p][cc] = Ab[(size_t)cc * npix + n0 + p];
            Bs[p][cc] = Bb[(size_t)cc * npix + n0 + p];
        }
        __syncthreads();
        for (int p = ps; p < 64; p += 4) {
            float av[8], bv[8];
#pragma unroll
            for (int u = 0; u < 8; u++) av[u] = As[p][i8 * 8 + u];
#pragma unroll
            for (int v = 0; v < 8; v++) bv[v] = Bs[p][j8 * 8 + v];
#pragma unroll
            for (int u = 0; u < 8; u++)
#pragma unroll
                for (int v = 0; v < 8; v++)
                    acc[u][v] += av[u] * bv[v];
        }
    }

    float* Gb = G + b * 4096;
#pragma unroll
    for (int u = 0; u < 8; u++)
#pragma unroll
        for (int v = 0; v < 8; v++)
            atomicAdd(&Gb[(i8 * 8 + u) * 64 + (j8 * 8 + v)], acc[u][v]);
}

// ---------------------------------------------------------------------------
// Solve the small per-batch algebra: produce M1, M2 (64x64 each).
// grid: (BATCH); block: 256
// ---------------------------------------------------------------------------
__global__ __launch_bounds__(256)
void solve_kernel(const float* __restrict__ qh_w, const float* __restrict__ kh_w,
                  const float* __restrict__ vh_w, const float* __restrict__ ql_w,
                  const float* __restrict__ kl_w, const float* __restrict__ vl_w,
                  const float* __restrict__ proj_w,
                  const float* __restrict__ aw1, const float* __restrict__ aw2,
                  const float* __restrict__ temp)
{
    __shared__ float sA[4096];
    __shared__ float sB[4096];
    __shared__ float sPooled[64], sHid[16], sAtt[64];
    __shared__ float sS[64 * 8], sNq[64], sNk[64], sP[256];

    int b = blockIdx.x, tid = threadIdx.x;

    // ---- high-frequency channel attention ----
    const float* Gh = g_Gh + b * 4096;
    for (int i = tid; i < 4096; i += 256) sA[i] = Gh[i];
    __syncthreads();
    // sB = qh_w @ Gh
    for (int i = tid; i < 4096; i += 256) {
        int r = i >> 6, c2 = i & 63; float s = 0.f;
        for (int c1 = 0; c1 < 64; c1++) s += qh_w[r * 64 + c1] * sA[c1 * 64 + c2];
        sB[i] = s;
    }
    __syncthreads();
    if (tid < 64) {
        float s = 0.f;
        for (int c2 = 0; c2 < 64; c2++) s += sB[tid * 64 + c2] * kh_w[tid * 64 + c2];
        sPooled[tid] = s * (1.f / (float)HW);
    }
    __syncthreads();
    if (tid < 16) {
        float s = 0.f;
        for (int c = 0; c < 64; c++) s += aw1[tid * 64 + c] * sPooled[c];
        sHid[tid] = fmaxf(s, 0.f);
    }
    __syncthreads();
    if (tid < 64) {
        float s = 0.f;
        for (int j = 0; j < 16; j++) s += aw2[tid * 16 + j] * sHid[j];
        sAtt[tid] = tanhf(s);
    }
    __syncthreads();

    // M1 = proj_w @ diag(att) @ vh_w
    for (int i = tid; i < 4096; i += 256) { int r = i >> 6; sA[i] = sAtt[r] * vh_w[i]; }
    __syncthreads();
    float* M1 = g_M + b * 8192;
    for (int i = tid; i < 4096; i += 256) {
        int o = i >> 6, c = i & 63; float s = 0.f;
        for (int k = 0; k < 64; k++) s += proj_w[o * 64 + k] * sA[k * 64 + c];
        M1[i] = s;
    }
    __syncthreads();

    // ---- low-frequency attention ----
    const float* Gxy = g_Gxy + b * 4096;
    for (int i = tid; i < 4096; i += 256) sA[i] = Gxy[i];
    __syncthreads();
    // sB = ql_w @ Gxy
    for (int i = tid; i < 4096; i += 256) {
        int r = i >> 6, c2 = i & 63; float s = 0.f;
        for (int c1 = 0; c1 < 64; c1++) s += ql_w[r * 64 + c1] * sA[c1 * 64 + c2];
        sB[i] = s;
    }
    __syncthreads();
    // S[i][j] = q_l[i] . k_l[j]   (j within i's head only)
    for (int i = tid; i < 512; i += 256) {
        int r = i >> 3, j = i & 7;
        int h = r >> 3;
        int kc = h * 8 + j;
        float s = 0.f;
        for (int c = 0; c < 64; c++) s += sB[r * 64 + c] * kl_w[kc * 64 + c];
        sS[i] = s;
    }
    __syncthreads();

    // ||q_l[i]||: quadratic form ql_w[i] Gxx ql_w[i]^T
    const float* Gxx = g_Gxx + b * 4096;
    for (int i = tid; i < 4096; i += 256) sA[i] = Gxx[i];
    __syncthreads();
    {
        int i = tid >> 2, pt = tid & 3;
        float s = 0.f;
        for (int c1 = pt * 16; c1 < pt * 16 + 16; c1++) {
            float w = ql_w[i * 64 + c1];
            float inner = 0.f;
            for (int c2 = 0; c2 < 64; c2++) inner += sA[c1 * 64 + c2] * ql_w[i * 64 + c2];
            s += w * inner;
        }
        sP[tid] = s;
    }
    __syncthreads();
    if (tid < 64) {
        float v = sP[tid * 4] + sP[tid * 4 + 1] + sP[tid * 4 + 2] + sP[tid * 4 + 3];
        sNq[tid] = fmaxf(sqrtf(fmaxf(v, 0.f)), 1e-12f);
    }
    __syncthreads();

    // ||k_l[j]||
    const float* Gyy = g_Gyy + b * 4096;
    for (int i = tid; i < 4096; i += 256) sA[i] = Gyy[i];
    __syncthreads();
    {
        int i = tid >> 2, pt = tid & 3;
        float s = 0.f;
        for (int c1 = pt * 16; c1 < pt * 16 + 16; c1++) {
            float w = kl_w[i * 64 + c1];
            float inner = 0.f;
            for (int c2 = 0; c2 < 64; c2++) inner += sA[c1 * 64 + c2] * kl_w[i * 64 + c2];
            s += w * inner;
        }
        sP[tid] = s;
    }
    __syncthreads();
    if (tid < 64) {
        float v = sP[tid * 4] + sP[tid * 4 + 1] + sP[tid * 4 + 2] + sP[tid * 4 + 3];
        sNk[tid] = fmaxf(sqrtf(fmaxf(v, 0.f)), 1e-12f);
    }
    __syncthreads();

    // softmax rows (8-wide within each head), temperature applied pre-softmax
    if (tid < 64) {
        int i = tid, h = i >> 3;
        float t = temp[h];
        float v[8];
#pragma unroll
        for (int j = 0; j < 8; j++)
            v[j] = sS[i * 8 + j] / (sNq[i] * sNk[h * 8 + j]) * t;
        float m = v[0];
#pragma unroll
        for (int j = 1; j < 8; j++) m = fmaxf(m, v[j]);
        float sum = 0.f;
#pragma unroll
        for (int j = 0; j < 8; j++) { v[j] = expf(v[j] - m); sum += v[j]; }
        float inv = 1.f / sum;
#pragma unroll
        for (int j = 0; j < 8; j++) sS[i * 8 + j] = v[j] * inv;
    }
    __syncthreads();

    // sA = A_blockdiag @ vl_w
    for (int i = tid; i < 4096; i += 256) {
        int r = i >> 6, c = i & 63;
        int h = r >> 3;
        float s = 0.f;
#pragma unroll
        for (int j = 0; j < 8; j++) s += sS[r * 8 + j] * vl_w[(h * 8 + j) * 64 + c];
        sA[i] = s;
    }
    __syncthreads();

    // M2 = proj_w @ sA
    float* M2 = g_M + b * 8192 + 4096;
    for (int i = tid; i < 4096; i += 256) {
        int o = i >> 6, c = i & 63; float s = 0.f;
        for (int k = 0; k < 64; k++) s += proj_w[o * 64 + k] * sA[k * 64 + c];
        M2[i] = s;
    }
}

// ---------------------------------------------------------------------------
// Final fused GEMM: out[b,o,n] = sum_c M1[o,c]*xh[b,c,n] + M2[o,c]*y[b,c,n]
// grid: (HW/256, BATCH); block 256.
// Thread layout: og (0..3) -> 16 outputs each, pg (0..63) -> 4 pixels each.
// M stored transposed in smem: sM[c*64 + o] for vectorized loads.
// ---------------------------------------------------------------------------
__global__ __launch_bounds__(256)
void final_kernel(const float* __restrict__ y, float* __restrict__ out)
{
    __shared__ float sM1[4096];
    __shared__ float sM2[4096];

    int b   = blockIdx.y;
    int n0  = blockIdx.x * 256;
    int tid = threadIdx.x;

    const float* M1 = g_M + b * 8192;
    const float* M2 = M1 + 4096;
    for (int idx = tid; idx < 4096; idx += 256) {
        int o = idx >> 6, c = idx & 63;
        sM1[c * 64 + o] = M1[idx];
        sM2[c * 64 + o] = M2[idx];
    }
    __syncthreads();

    int og = tid >> 6;        // 0..3 -> outputs og*16 .. og*16+15
    int pg = tid & 63;        // pixels n0 + pg*4 .. +3

    const float* xb = g_xh + (size_t)b * CH * HW + n0 + pg * 4;
    const float* yb = y    + (size_t)b * CH * HW + n0 + pg * 4;

    float acc[16][4];
#pragma unroll
    for (int u = 0; u < 16; u++)
#pragma unroll
        for (int v = 0; v < 4; v++) acc[u][v] = 0.f;

    for (int c = 0; c < 64; c++) {
        float4 xv = __ldg((const float4*)(xb + (size_t)c * HW));
        float4 yv = __ldg((const float4*)(yb + (size_t)c * HW));
        const float4* m1p = (const float4*)&sM1[c * 64 + og * 16];
        const float4* m2p = (const float4*)&sM2[c * 64 + og * 16];
#pragma unroll
        for (int q = 0; q < 4; q++) {
            float4 m1 = m1p[q];
            float4 m2 = m2p[q];
            acc[q * 4 + 0][0] += m1.x * xv.x + m2.x * yv.x;
            acc[q * 4 + 0][1] += m1.x * xv.y + m2.x * yv.y;
            acc[q * 4 + 0][2] += m1.x * xv.z + m2.x * yv.z;
            acc[q * 4 + 0][3] += m1.x * xv.w + m2.x * yv.w;
            acc[q * 4 + 1][0] += m1.y * xv.x + m2.y * yv.x;
            acc[q * 4 + 1][1] += m1.y * xv.y + m2.y * yv.y;
            acc[q * 4 + 1][2] += m1.y * xv.z + m2.y * yv.z;
            acc[q * 4 + 1][3] += m1.y * xv.w + m2.y * yv.w;
            acc[q * 4 + 2][0] += m1.z * xv.x + m2.z * yv.x;
            acc[q * 4 + 2][1] += m1.z * xv.y + m2.z * yv.y;
            acc[q * 4 + 2][2] += m1.z * xv.z + m2.z * yv.z;
            acc[q * 4 + 2][3] += m1.z * xv.w + m2.z * yv.w;
            acc[q * 4 + 3][0] += m1.w * xv.x + m2.w * yv.x;
            acc[q * 4 + 3][1] += m1.w * xv.y + m2.w * yv.y;
            acc[q * 4 + 3][2] += m1.w * xv.z + m2.w * yv.z;
            acc[q * 4 + 3][3] += m1.w * xv.w + m2.w * yv.w;
        }
    }

    float* ob = out + (size_t)b * CH * HW + n0 + pg * 4;
#pragma unroll
    for (int u = 0; u < 16; u++) {
        int o = og * 16 + u;
        *((float4*)(ob + (size_t)o * HW)) =
            make_float4(acc[u][0], acc[u][1], acc[u][2], acc[u][3]);
    }
}

// ---------------------------------------------------------------------------
// Launch
// ---------------------------------------------------------------------------
extern "C" void kernel_launch(void* const* d_in, const int* in_sizes, int n_in,
                              void* d_out, int out_size)
{
    const float* x       = (const float*)d_in[0];
    const float* y       = (const float*)d_in[1];
    const float* hp1_w3  = (const float*)d_in[2];
    const float* hp1_w5  = (const float*)d_in[3];
    const float* hp1_w7  = (const float*)d_in[4];
    const float* hp2_w3  = (const float*)d_in[5];
    const float* hp2_w5  = (const float*)d_in[6];
    const float* hp2_w7  = (const float*)d_in[7];
    const float* qh_w    = (const float*)d_in[8];
    const float* kh_w    = (const float*)d_in[9];
    const float* vh_w    = (const float*)d_in[10];
    const float* ql_w    = (const float*)d_in[11];
    const float* kl_w    = (const float*)d_in[12];
    const float* vl_w    = (const float*)d_in[13];
    const float* proj_w  = (const float*)d_in[14];
    const float* attn_w1 = (const float*)d_in[15];
    const float* attn_w2 = (const float*)d_in[16];
    const float* temp    = (const float*)d_in[17];
    float* out = (float*)d_out;

    zero_kernel<<<64, 256>>>();

    dim3 dwgrid(16, CH, BATCH);
    dwpool_kernel<<<dwgrid, 256>>>(x, hp1_w3, hp1_w5, hp1_w7, 0);
    dwpool_kernel<<<dwgrid, 256>>>(y, hp2_w3, hp2_w5, hp2_w7, 1);

    gram64_kernel<<<dim3(32, BATCH), 256>>>(0, HW, 32);   // Gh
    gram64_kernel<<<dim3(16, BATCH), 256>>>(1, HWP, 16);  // Gxy
    gram64_kernel<<<dim3(16, BATCH), 256>>>(2, HWP, 16);  // Gxx
    gram64_kernel<<<dim3(16, BATCH), 256>>>(3, HWP, 16);  // Gyy

    solve_kernel<<<BATCH, 256>>>(qh_w, kh_w, vh_w, ql_w, kl_w, vl_w,
                                 proj_w, attn_w1, attn_w2, temp);

    final_kernel<<<dim3(HW / 256, BATCH), 256>>>(y, out);
}

// round 3
// speedup vs baseline: 1.2015x; 1.2015x over previous
#include <cuda_runtime.h>
#include <cuda_bf16.h>
#include <math.h>

// Problem constants
#define BATCH   4
#define CH      64
#define IMG_W   256
#define IMG_H   256
#define HW      (IMG_W * IMG_H)        // 65536
#define WP      128
#define HWP     (WP * WP)              // 16384

// ---------------------------------------------------------------------------
// Static device scratch (no runtime allocation allowed)
// ---------------------------------------------------------------------------
__device__ float g_xh[BATCH * CH * HW];    // DW1(x)
__device__ float g_yh[BATCH * CH * HW];    // DW2(y)
__device__ float g_xp[BATCH * CH * HWP];   // avgpool2(x)
__device__ float g_yp[BATCH * CH * HWP];   // avgpool2(y)
__device__ float g_Gh [BATCH * 4096];      // xh · yh^T
__device__ float g_Gxy[BATCH * 4096];      // xp · yp^T
__device__ float g_Gxx[BATCH * 4096];      // xp · xp^T
__device__ float g_Gyy[BATCH * 4096];      // yp · yp^T
__device__ float g_M  [BATCH * 2 * 4096];  // per batch: M1 (4096), M2 (4096)

// ---------------------------------------------------------------------------
// zero the gram accumulators
// ---------------------------------------------------------------------------
__global__ void zero_kernel() {
    int i = blockIdx.x * blockDim.x + threadIdx.x;
    if (i < BATCH * 4096) {
        g_Gh[i] = 0.f; g_Gxy[i] = 0.f; g_Gxx[i] = 0.f; g_Gyy[i] = 0.f;
    }
}

// ---------------------------------------------------------------------------
// Depthwise conv (k=3/5/7 per channel group) + 2x2 avg pool of the raw input.
// grid: (16 tiles, 64 channels, 4 batches); block: 256
// sel = 0 -> write g_xh/g_xp, sel = 1 -> write g_yh/g_yp
// ---------------------------------------------------------------------------
template<int K>
__device__ __forceinline__ void dw_compute(const float* __restrict__ s,
                                           const float* __restrict__ wp,
                                           float* __restrict__ outh,
                                           int ty0, int tx0, int tid)
{
    float wr[K * K];
#pragma unroll
    for (int t = 0; t < K * K; t++) wr[t] = __ldg(&wp[t]);

    int col = tid & 63;
    int rb  = tid >> 6;
#pragma unroll 4
    for (int i = 0; i < 16; i++) {
        int row = rb + 4 * i;
        float acc = 0.f;
#pragma unroll
        for (int dy = 0; dy < K; dy++) {
#pragma unroll
            for (int dx = 0; dx < K; dx++) {
                acc += wr[dy * K + dx] *
                       s[(row + 3 - K / 2 + dy) * 70 + (col + 3 - K / 2 + dx)];
            }
        }
        outh[(ty0 + row) * IMG_W + tx0 + col] = acc;
    }
}

__global__ __launch_bounds__(256)
void dwpool_kernel(const float* __restrict__ img,
                   const float* __restrict__ w3,
                   const float* __restrict__ w5,
                   const float* __restrict__ w7,
                   int sel)
{
    __shared__ float s[70 * 70];
    int tile = blockIdx.x;          // 0..15 (4x4 tiles of 64x64)
    int c    = blockIdx.y;
    int b    = blockIdx.z;
    int tid  = threadIdx.x;

    int ty0 = (tile >> 2) * 64;
    int tx0 = (tile & 3) * 64;

    const float* base = img + ((size_t)(b * CH + c)) * HW;

    for (int idx = tid; idx < 70 * 70; idx += 256) {
        int r  = idx / 70, q = idx % 70;
        int gy = ty0 + r - 3, gx = tx0 + q - 3;
        float v = 0.f;
        if (gy >= 0 && gy < IMG_H && gx >= 0 && gx < IMG_W)
            v = __ldg(&base[gy * IMG_W + gx]);
        s[idx] = v;
    }
    __syncthreads();

    float* outh = (sel == 0 ? g_xh : g_yh) + ((size_t)(b * CH + c)) * HW;
    float* outp = (sel == 0 ? g_xp : g_yp) + ((size_t)(b * CH + c)) * HWP;

    if (c < 32) {
        dw_compute<3>(s, w3 + c * 9, outh, ty0, tx0, tid);
    } else if (c < 48) {
        dw_compute<5>(s, w5 + (c - 32) * 25, outh, ty0, tx0, tid);
    } else {
        dw_compute<7>(s, w7 + (c - 48) * 49, outh, ty0, tx0, tid);
    }

    // 2x2 average pooling of raw input from smem (32x32 pooled values per tile)
    int pty0 = ty0 >> 1, ptx0 = tx0 >> 1;
#pragma unroll
    for (int i = 0; i < 4; i++) {
        int p  = tid + 256 * i;          // 0..1023
        int pr = p >> 5, pc = p & 31;
        float v = 0.25f * (s[(2 * pr + 3) * 70 + (2 * pc + 3)] +
                           s[(2 * pr + 3) * 70 + (2 * pc + 4)] +
                           s[(2 * pr + 4) * 70 + (2 * pc + 3)] +
                           s[(2 * pr + 4) * 70 + (2 * pc + 4)]);
        outp[(pty0 + pr) * WP + ptx0 + pc] = v;
    }
}

// ---------------------------------------------------------------------------
// Fused Gram kernel: G[b][c1][c2] = sum_n A[b][c1][n] * B[b][c2][n]
// blockIdx.z: 0 -> (xh,yh)->Gh (npix=HW)   1 -> (xp,yp)->Gxy
//             2 -> (xp,xp)->Gxx            3 -> (yp,yp)->Gyy  (npix=HWP)
// grid: (CHUNKS, BATCH, 4); block 256.
// Thread (i8,j8,ps): accumulates G[(u*8+i8)][(v*8+j8)] over pixel slice ps.
// Channel mapping u*8+i8 / v*8+j8 makes the lane index the fast (bank)
// dimension -> conflict-free smem reads.
// Partials across the 4 ps-slices are reduced in smem before global atomics.
// ---------------------------------------------------------------------------
#define GRAM_CHUNKS 128

__global__ __launch_bounds__(256)
void gram_all_kernel()
{
    __shared__ float As[64][65];
    __shared__ float Bs[64][65];

    int which = blockIdx.z;
    const float* A; const float* Bm; float* G; int npix;
    if (which == 0)      { A = g_xh; Bm = g_yh; G = g_Gh;  npix = HW;  }
    else if (which == 1) { A = g_xp; Bm = g_yp; G = g_Gxy; npix = HWP; }
    else if (which == 2) { A = g_xp; Bm = g_xp; G = g_Gxx; npix = HWP; }
    else                 { A = g_yp; Bm = g_yp; G = g_Gyy; npix = HWP; }

    int b   = blockIdx.y;
    int tid = threadIdx.x;
    int per = npix / GRAM_CHUNKS;          // 512 (Gh) or 128 (pooled)
    int n_start = blockIdx.x * per;
    int n_end   = n_start + per;

    const float* Ab = A  + (size_t)b * CH * npix;
    const float* Bb = Bm + (size_t)b * CH * npix;

    int i8 = (tid >> 3) & 7;   // c1 offset within group of 8
    int j8 = tid & 7;          // c2 offset within group of 8
    int ps = tid >> 6;         // pixel slice 0..3

    float acc[8][8];
#pragma unroll
    for (int u = 0; u < 8; u++)
#pragma unroll
        for (int v = 0; v < 8; v++) acc[u][v] = 0.f;

    for (int n0 = n_start; n0 < n_end; n0 += 64) {
        __syncthreads();
        for (int idx = tid; idx < 4096; idx += 256) {
            int cc = idx >> 6, p = idx & 63;
            As[p][cc] = Ab[(size_t)cc * npix + n0 + p];
            Bs[p][cc] = Bb[(size_t)cc * npix + n0 + p];
        }
        __syncthreads();
        for (int p = ps; p < 64; p += 4) {
            float av[8], bv[8];
#pragma unroll
            for (int u = 0; u < 8; u++) av[u] = As[p][u * 8 + i8];
#pragma unroll
            for (int v = 0; v < 8; v++) bv[v] = Bs[p][v * 8 + j8];
#pragma unroll
            for (int u = 0; u < 8; u++)
#pragma unroll
                for (int v = 0; v < 8; v++)
                    acc[u][v] += av[u] * bv[v];
        }
    }

    // reduce the 4 ps-slices in smem, then one atomic per element per block
    float* red = &As[0][0];    // 4160 floats >= 4096, As no longer needed
    __syncthreads();
    for (int i = tid; i < 4096; i += 256) red[i] = 0.f;
    __syncthreads();
#pragma unroll
    for (int u = 0; u < 8; u++)
#pragma unroll
        for (int v = 0; v < 8; v++)
            atomicAdd(&red[(u * 8 + i8) * 64 + (v * 8 + j8)], acc[u][v]);
    __syncthreads();

    float* Gb = G + b * 4096;
    for (int i = tid; i < 4096; i += 256)
        atomicAdd(&Gb[i], red[i]);
}

// ---------------------------------------------------------------------------
// Solve the small per-batch algebra: produce M1, M2 (64x64 each).
// grid: (BATCH); block: 256
// ---------------------------------------------------------------------------
__global__ __launch_bounds__(256)
void solve_kernel(const float* __restrict__ qh_w, const float* __restrict__ kh_w,
                  const float* __restrict__ vh_w, const float* __restrict__ ql_w,
                  const float* __restrict__ kl_w, const float* __restrict__ vl_w,
                  const float* __restrict__ proj_w,
                  const float* __restrict__ aw1, const float* __restrict__ aw2,
                  const float* __restrict__ temp)
{
    __shared__ float sA[4096];
    __shared__ float sB[4096];
    __shared__ float sPooled[64], sHid[16], sAtt[64];
    __shared__ float sS[64 * 8], sNq[64], sNk[64], sP[256];

    int b = blockIdx.x, tid = threadIdx.x;

    // ---- high-frequency channel attention ----
    const float* Gh = g_Gh + b * 4096;
    for (int i = tid; i < 4096; i += 256) sA[i] = Gh[i];
    __syncthreads();
    // sB = qh_w @ Gh
    for (int i = tid; i < 4096; i += 256) {
        int r = i >> 6, c2 = i & 63; float s = 0.f;
        for (int c1 = 0; c1 < 64; c1++) s += qh_w[r * 64 + c1] * sA[c1 * 64 + c2];
        sB[i] = s;
    }
    __syncthreads();
    if (tid < 64) {
        float s = 0.f;
        for (int c2 = 0; c2 < 64; c2++) s += sB[tid * 64 + c2] * kh_w[tid * 64 + c2];
        sPooled[tid] = s * (1.f / (float)HW);
    }
    __syncthreads();
    if (tid < 16) {
        float s = 0.f;
        for (int c = 0; c < 64; c++) s += aw1[tid * 64 + c] * sPooled[c];
        sHid[tid] = fmaxf(s, 0.f);
    }
    __syncthreads();
    if (tid < 64) {
        float s = 0.f;
        for (int j = 0; j < 16; j++) s += aw2[tid * 16 + j] * sHid[j];
        sAtt[tid] = tanhf(s);
    }
    __syncthreads();

    // M1 = proj_w @ diag(att) @ vh_w
    for (int i = tid; i < 4096; i += 256) { int r = i >> 6; sA[i] = sAtt[r] * vh_w[i]; }
    __syncthreads();
    float* M1 = g_M + b * 8192;
    for (int i = tid; i < 4096; i += 256) {
        int o = i >> 6, c = i & 63; float s = 0.f;
        for (int k = 0; k < 64; k++) s += proj_w[o * 64 + k] * sA[k * 64 + c];
        M1[i] = s;
    }
    __syncthreads();

    // ---- low-frequency attention ----
    const float* Gxy = g_Gxy + b * 4096;
    for (int i = tid; i < 4096; i += 256) sA[i] = Gxy[i];
    __syncthreads();
    // sB = ql_w @ Gxy
    for (int i = tid; i < 4096; i += 256) {
        int r = i >> 6, c2 = i & 63; float s = 0.f;
        for (int c1 = 0; c1 < 64; c1++) s += ql_w[r * 64 + c1] * sA[c1 * 64 + c2];
        sB[i] = s;
    }
    __syncthreads();
    // S[i][j] = q_l[i] . k_l[j]   (j within i's head only)
    for (int i = tid; i < 512; i += 256) {
        int r = i >> 3, j = i & 7;
        int h = r >> 3;
        int kc = h * 8 + j;
        float s = 0.f;
        for (int c = 0; c < 64; c++) s += sB[r * 64 + c] * kl_w[kc * 64 + c];
        sS[i] = s;
    }
    __syncthreads();

    // ||q_l[i]||: quadratic form ql_w[i] Gxx ql_w[i]^T
    const float* Gxx = g_Gxx + b * 4096;
    for (int i = tid; i < 4096; i += 256) sA[i] = Gxx[i];
    __syncthreads();
    {
        int i = tid >> 2, pt = tid & 3;
        float s = 0.f;
        for (int c1 = pt * 16; c1 < pt * 16 + 16; c1++) {
            float w = ql_w[i * 64 + c1];
            float inner = 0.f;
            for (int c2 = 0; c2 < 64; c2++) inner += sA[c1 * 64 + c2] * ql_w[i * 64 + c2];
            s += w * inner;
        }
        sP[tid] = s;
    }
    __syncthreads();
    if (tid < 64) {
        float v = sP[tid * 4] + sP[tid * 4 + 1] + sP[tid * 4 + 2] + sP[tid * 4 + 3];
        sNq[tid] = fmaxf(sqrtf(fmaxf(v, 0.f)), 1e-12f);
    }
    __syncthreads();

    // ||k_l[j]||
    const float* Gyy = g_Gyy + b * 4096;
    for (int i = tid; i < 4096; i += 256) sA[i] = Gyy[i];
    __syncthreads();
    {
        int i = tid >> 2, pt = tid & 3;
        float s = 0.f;
        for (int c1 = pt * 16; c1 < pt * 16 + 16; c1++) {
            float w = kl_w[i * 64 + c1];
            float inner = 0.f;
            for (int c2 = 0; c2 < 64; c2++) inner += sA[c1 * 64 + c2] * kl_w[i * 64 + c2];
            s += w * inner;
        }
        sP[tid] = s;
    }
    __syncthreads();
    if (tid < 64) {
        float v = sP[tid * 4] + sP[tid * 4 + 1] + sP[tid * 4 + 2] + sP[tid * 4 + 3];
        sNk[tid] = fmaxf(sqrtf(fmaxf(v, 0.f)), 1e-12f);
    }
    __syncthreads();

    // softmax rows (8-wide within each head), temperature applied pre-softmax
    if (tid < 64) {
        int i = tid, h = i >> 3;
        float t = temp[h];
        float v[8];
#pragma unroll
        for (int j = 0; j < 8; j++)
            v[j] = sS[i * 8 + j] / (sNq[i] * sNk[h * 8 + j]) * t;
        float m = v[0];
#pragma unroll
        for (int j = 1; j < 8; j++) m = fmaxf(m, v[j]);
        float sum = 0.f;
#pragma unroll
        for (int j = 0; j < 8; j++) { v[j] = expf(v[j] - m); sum += v[j]; }
        float inv = 1.f / sum;
#pragma unroll
        for (int j = 0; j < 8; j++) sS[i * 8 + j] = v[j] * inv;
    }
    __syncthreads();

    // sA = A_blockdiag @ vl_w
    for (int i = tid; i < 4096; i += 256) {
        int r = i >> 6, c = i & 63;
        int h = r >> 3;
        float s = 0.f;
#pragma unroll
        for (int j = 0; j < 8; j++) s += sS[r * 8 + j] * vl_w[(h * 8 + j) * 64 + c];
        sA[i] = s;
    }
    __syncthreads();

    // M2 = proj_w @ sA
    float* M2 = g_M + b * 8192 + 4096;
    for (int i = tid; i < 4096; i += 256) {
        int o = i >> 6, c = i & 63; float s = 0.f;
        for (int k = 0; k < 64; k++) s += proj_w[o * 64 + k] * sA[k * 64 + c];
        M2[i] = s;
    }
}

// ---------------------------------------------------------------------------
// Final fused GEMM: out[b,o,n] = sum_c M1[o,c]*xh[b,c,n] + M2[o,c]*y[b,c,n]
// grid: (HW/256, BATCH); block 256.
// Thread layout: og = tid>>5 (8 outputs each), pg = tid&31 (8 pixels each).
// All 32 lanes of a warp share og -> every sM read is a warp broadcast.
// ---------------------------------------------------------------------------
__global__ __launch_bounds__(256)
void final_kernel(const float* __restrict__ y, float* __restrict__ out)
{
    __shared__ float sM1[4096];   // [c][o]
    __shared__ float sM2[4096];

    int b   = blockIdx.y;
    int n0  = blockIdx.x * 256;
    int tid = threadIdx.x;

    const float* M1 = g_M + b * 8192;
    const float* M2 = M1 + 4096;
    for (int idx = tid; idx < 4096; idx += 256) {
        int o = idx >> 6, c = idx & 63;
        sM1[c * 64 + o] = M1[idx];
        sM2[c * 64 + o] = M2[idx];
    }
    __syncthreads();

    int og = tid >> 5;        // 0..7 -> outputs og*8 .. og*8+7 (uniform per warp)
    int pg = tid & 31;        // pixels n0 + pg*8 .. +7

    const float* xb = g_xh + (size_t)b * CH * HW + n0 + pg * 8;
    const float* yb = y    + (size_t)b * CH * HW + n0 + pg * 8;

    float acc[8][8];
#pragma unroll
    for (int u = 0; u < 8; u++)
#pragma unroll
        for (int v = 0; v < 8; v++) acc[u][v] = 0.f;

    for (int c = 0; c < 64; c++) {
        float4 xv0 = __ldg((const float4*)(xb + (size_t)c * HW));
        float4 xv1 = __ldg((const float4*)(xb + (size_t)c * HW + 4));
        float4 yv0 = __ldg((const float4*)(yb + (size_t)c * HW));
        float4 yv1 = __ldg((const float4*)(yb + (size_t)c * HW + 4));
        float xr[8] = {xv0.x, xv0.y, xv0.z, xv0.w, xv1.x, xv1.y, xv1.z, xv1.w};
        float yr[8] = {yv0.x, yv0.y, yv0.z, yv0.w, yv1.x, yv1.y, yv1.z, yv1.w};
        const float4* m1p = (const float4*)&sM1[c * 64 + og * 8];
        const float4* m2p = (const float4*)&sM2[c * 64 + og * 8];
        float4 m1a = m1p[0], m1b = m1p[1];
        float4 m2a = m2p[0], m2b = m2p[1];
        float m1r[8] = {m1a.x, m1a.y, m1a.z, m1a.w, m1b.x, m1b.y, m1b.z, m1b.w};
        float m2r[8] = {m2a.x, m2a.y, m2a.z, m2a.w, m2b.x, m2b.y, m2b.z, m2b.w};
#pragma unroll
        for (int u = 0; u < 8; u++)
#pragma unroll
            for (int v = 0; v < 8; v++)
                acc[u][v] += m1r[u] * xr[v] + m2r[u] * yr[v];
    }

    float* ob = out + (size_t)b * CH * HW + n0 + pg * 8;
#pragma unroll
    for (int u = 0; u < 8; u++) {
        int o = og * 8 + u;
        *((float4*)(ob + (size_t)o * HW)) =
            make_float4(acc[u][0], acc[u][1], acc[u][2], acc[u][3]);
        *((float4*)(ob + (size_t)o * HW + 4)) =
            make_float4(acc[u][4], acc[u][5], acc[u][6], acc[u][7]);
    }
}

// ---------------------------------------------------------------------------
// Launch
// ---------------------------------------------------------------------------
extern "C" void kernel_launch(void* const* d_in, const int* in_sizes, int n_in,
                              void* d_out, int out_size)
{
    const float* x       = (const float*)d_in[0];
    const float* y       = (const float*)d_in[1];
    const float* hp1_w3  = (const float*)d_in[2];
    const float* hp1_w5  = (const float*)d_in[3];
    const float* hp1_w7  = (const float*)d_in[4];
    const float* hp2_w3  = (const float*)d_in[5];
    const float* hp2_w5  = (const float*)d_in[6];
    const float* hp2_w7  = (const float*)d_in[7];
    const float* qh_w    = (const float*)d_in[8];
    const float* kh_w    = (const float*)d_in[9];
    const float* vh_w    = (const float*)d_in[10];
    const float* ql_w    = (const float*)d_in[11];
    const float* kl_w    = (const float*)d_in[12];
    const float* vl_w    = (const float*)d_in[13];
    const float* proj_w  = (const float*)d_in[14];
    const float* attn_w1 = (const float*)d_in[15];
    const float* attn_w2 = (const float*)d_in[16];
    const float* temp    = (const float*)d_in[17];
    float* out = (float*)d_out;

    zero_kernel<<<64, 256>>>();

    dim3 dwgrid(16, CH, BATCH);
    dwpool_kernel<<<dwgrid, 256>>>(x, hp1_w3, hp1_w5, hp1_w7, 0);
    dwpool_kernel<<<dwgrid, 256>>>(y, hp2_w3, hp2_w5, hp2_w7, 1);

    gram_all_kernel<<<dim3(GRAM_CHUNKS, BATCH, 4), 256>>>();

    solve_kernel<<<BATCH, 256>>>(qh_w, kh_w, vh_w, ql_w, kl_w, vl_w,
                                 proj_w, attn_w1, attn_w2, temp);

    final_kernel<<<dim3(HW / 256, BATCH), 256>>>(y, out);
}